// round 11
// baseline (speedup 1.0000x reference)
#include <cuda_runtime.h>
#include <cuda_bf16.h>

// MaxPool2d k=2 s=2 on fp32 NCHW (32, 96, 224, 224) -> (32, 96, 112, 112).
// DRAM-controller-bound at ~7.05 TB/s (88-89% of spec); five structurally
// distinct variants all within 0.03% of 109.3 us. Traffic minimal (771 MB).
//
// This round: persistent grid-stride (exactly one wave: 148 SMs x 8 CTAs x
// 256 thr) to eliminate ~42 wave transitions; 2-deep unroll -> 8 independent
// LDG.128 in flight per thread. Flat-index striding preserves perfect
// coalescing (consecutive threads = consecutive output float4s).

#define NC_     3072
#define W_      224
#define OH_     112
#define OW4_    28                 // float4s per output row
#define ROWF4_  (W_ / 4)           // 56 float4s per input row
#define TOTAL_  (NC_ * OH_ * OW4_) // 9,633,792 output float4s

#define NBLK_    1184              // 148 SMs * 8 resident CTAs
#define NTHR_    256
#define GSTRIDE_ (NBLK_ * NTHR_)   // 303,104; TOTAL_ / GSTRIDE_ = 31.78

__device__ __forceinline__ float4 pool_one(const float4* __restrict__ x,
                                           unsigned int idx) {
    unsigned int ox4 = idx % OW4_;
    unsigned int t   = idx / OW4_;
    unsigned int oy  = t % OH_;
    unsigned int nc  = t / OH_;

    size_t base = (size_t)nc * (W_ * W_ / 4) + (size_t)(2u * oy) * ROWF4_ + 2u * ox4;

    float4 a0 = __ldcs(x + base);
    float4 a1 = __ldcs(x + base + 1);
    float4 b0 = __ldcs(x + base + ROWF4_);
    float4 b1 = __ldcs(x + base + ROWF4_ + 1);

    float4 r;
    r.x = fmaxf(fmaxf(a0.x, a0.y), fmaxf(b0.x, b0.y));
    r.y = fmaxf(fmaxf(a0.z, a0.w), fmaxf(b0.z, b0.w));
    r.z = fmaxf(fmaxf(a1.x, a1.y), fmaxf(b1.x, b1.y));
    r.w = fmaxf(fmaxf(a1.z, a1.w), fmaxf(b1.z, b1.w));
    return r;
}

__global__ __launch_bounds__(NTHR_)
void maxpool2x2_kernel(const float4* __restrict__ x, float4* __restrict__ out) {
    unsigned int idx = blockIdx.x * NTHR_ + threadIdx.x;

    // Main loop: 2-way unrolled, 8 independent LDG.128 in flight.
    while (idx + GSTRIDE_ < TOTAL_) {
        float4 r0 = pool_one(x, idx);
        float4 r1 = pool_one(x, idx + GSTRIDE_);
        __stcs(out + idx, r0);
        __stcs(out + idx + GSTRIDE_, r1);
        idx += 2u * GSTRIDE_;
    }
    // Remainder (at most one element per thread).
    if (idx < TOTAL_) {
        __stcs(out + idx, pool_one(x, idx));
    }
}

extern "C" void kernel_launch(void* const* d_in, const int* in_sizes, int n_in,
                              void* d_out, int out_size) {
    const float4* x = (const float4*)d_in[0];
    float4* out = (float4*)d_out;
    maxpool2x2_kernel<<<NBLK_, NTHR_>>>(x, out);
}

// round 14
// speedup vs baseline: 1.0886x; 1.0886x over previous
#include <cuda_runtime.h>
#include <cuda_bf16.h>

// MaxPool2d k=2 s=2 on fp32 NCHW (32, 96, 224, 224) -> (32, 96, 112, 112).
// FINAL (resubmit after R12 infra failure; identical to the R7-validated shape).
// DRAM-controller-bound at ~7.07 TB/s (88-89% of 8 TB/s spec).
// Evidence: six non-persistent variants (load width 128/256b, store width
// 128/256b, +/- evict-first, occ 60-80%, blk 256/512) all within 0.03% of
// 109.3 us with occ/issue/L1/L2 far below their limits; the persistent
// grid-stride variant regressed (118.7 us, DRAM 81.7%) by reducing exposed
// memory parallelism. Traffic is information-theoretically minimal (771 MB).
//
// Shape: one thread per output float4, 2x LDG.128 per input row + 1x STG.128
// (evict-first streaming hints), 512-thread blocks, 18,816 blocks;
// grid divides exactly (9,633,792 = 512 * 18816) so no bounds check.

#define NC_    3072
#define W_     224
#define OH_    112
#define OW4_   28            // float4s per output row
#define ROWF4_ (W_ / 4)      // 56 float4s per input row
#define TOTAL_ (NC_ * OH_ * OW4_)   // 9,633,792 = 512 * 18816 exactly

__global__ __launch_bounds__(512)
void maxpool2x2_kernel(const float4* __restrict__ x, float4* __restrict__ out) {
    unsigned int idx = blockIdx.x * 512u + threadIdx.x;   // == output float4 index

    unsigned int ox4 = idx % OW4_;           // float4 within output row
    unsigned int t   = idx / OW4_;
    unsigned int oy  = t % OH_;
    unsigned int nc  = t / OH_;

    // Input as float4 indices: plane = nc*12544, rows 2*oy / 2*oy+1, col 2*ox4.
    size_t base = (size_t)nc * (W_ * W_ / 4) + (size_t)(2u * oy) * ROWF4_ + 2u * ox4;

    float4 a0 = __ldcs(x + base);               // row 2*oy,   floats [8*ox4 .. +3]
    float4 a1 = __ldcs(x + base + 1);           // row 2*oy,   floats [+4 .. +7]
    float4 b0 = __ldcs(x + base + ROWF4_);      // row 2*oy+1, floats [8*ox4 .. +3]
    float4 b1 = __ldcs(x + base + ROWF4_ + 1);  // row 2*oy+1, floats [+4 .. +7]

    float4 r;
    r.x = fmaxf(fmaxf(a0.x, a0.y), fmaxf(b0.x, b0.y));
    r.y = fmaxf(fmaxf(a0.z, a0.w), fmaxf(b0.z, b0.w));
    r.z = fmaxf(fmaxf(a1.x, a1.y), fmaxf(b1.x, b1.y));
    r.w = fmaxf(fmaxf(a1.z, a1.w), fmaxf(b1.z, b1.w));

    __stcs(out + idx, r);
}

extern "C" void kernel_launch(void* const* d_in, const int* in_sizes, int n_in,
                              void* d_out, int out_size) {
    const float4* x = (const float4*)d_in[0];
    float4* out = (float4*)d_out;
    maxpool2x2_kernel<<<TOTAL_ / 512, 512>>>(x, out);
}